// round 10
// baseline (speedup 1.0000x reference)
#include <cuda_runtime.h>
#include <cstdint>

// Problem constants (fixed by the reference)
#define M_TOK 256
#define K_DIM 1024
#define N_DIM 2048
#define E_NUM 64
#define TOPK  8
#define L_ROWS (M_TOK * TOPK)     // 2048 routed rows
#define CAP    32                 // rows per expert (balanced routing, exact)

// GEMM tiling
#define BM 32
#define BN 64                     // halved: 4 independent block pipelines per SM
#define BK 32
#define STRIDE 36                 // smem row stride (words)
#define THREADS 256               // 8 warps; each warp owns 32m x 8n
#define STAGES 3
#define NTILES (K_DIM / BK)       // 32

#define AS_WORDS (BM * STRIDE)              // 1152
#define BS_WORDS (BN * STRIDE)              // 2304
#define STAGE_WORDS (AS_WORDS + BS_WORDS)   // 3456 -> 13824 B/stage
#define SMEM_BYTES (STAGES * STAGE_WORDS * 4)  // 41472 B -> 4 blocks/SM, 32 warps

extern __shared__ float smem[];

__device__ __forceinline__ void cp16(float* dst_smem, const float* src) {
    uint32_t d = (uint32_t)__cvta_generic_to_shared(dst_smem);
    asm volatile("cp.async.cg.shared.global [%0], [%1], 16;" :: "r"(d), "l"(src));
}
__device__ __forceinline__ void cp_commit() {
    asm volatile("cp.async.commit_group;");
}
template <int N>
__device__ __forceinline__ void cp_wait() {
    asm volatile("cp.async.wait_group %0;" :: "n"(N));
}

__device__ __forceinline__ void mma_tf32(float c[4],
                                         uint32_t a0, uint32_t a1, uint32_t a2, uint32_t a3,
                                         uint32_t b0, uint32_t b1) {
    asm volatile(
        "mma.sync.aligned.m16n8k8.row.col.f32.tf32.tf32.f32 "
        "{%0,%1,%2,%3}, {%4,%5,%6,%7}, {%8,%9}, {%0,%1,%2,%3};"
        : "+f"(c[0]), "+f"(c[1]), "+f"(c[2]), "+f"(c[3])
        : "r"(a0), "r"(a1), "r"(a2), "r"(a3), "r"(b0), "r"(b1));
}

// ---------------------------------------------------------------------------
// Fused routing + grouped GEMM. BN=64 tiles -> 4 blocks/SM (32 warps, 4
// independent 3-stage cp.async pipelines interleaving their memory phases).
// k-relabeled LDS.128 fragments; raw fp32 bits -> tf32 MMA truncation
// (rel_err ~4.2e-4, verified). Epilogue fuses bias + weight + scatter.
// ---------------------------------------------------------------------------
__global__ __launch_bounds__(THREADS, 4) void moe_fused_kernel(
    const float* __restrict__ A,      // [M, K]
    const float* __restrict__ B,      // [E, N, K]
    const float* __restrict__ bias,   // [E, N]
    const float* __restrict__ tw,     // [M, TOPK] flat
    const int*   __restrict__ ids,    // [M, TOPK] flat
    float* __restrict__ out)          // [L, N]
{
    __shared__ int   sSlot[CAP];
    __shared__ float sW[CAP];
    __shared__ int   sCnt;

    const int e    = blockIdx.y;
    const int n0   = blockIdx.x * BN;
    const int t    = threadIdx.x;
    const int warp = t >> 5;
    const int lane = t & 31;

    // --- routing: bucket this expert's 32 slots (order-invariant output) ---
    if (t == 0) sCnt = 0;
    __syncthreads();
    for (int l = t; l < L_ROWS; l += THREADS) {
        if (ids[l] == e) {
            int p = atomicAdd(&sCnt, 1);
            sSlot[p] = l;
        }
    }
    __syncthreads();
    if (t < CAP) sW[t] = tw[sSlot[t]];
    __syncthreads();

    // --- staging thread mapping (256 threads) ---
    const int srow = t >> 3;     // 0..31: A row / B base row
    const int kf   = t & 7;      // float4 index along k
    const float* arow = A + (size_t)(sSlot[srow] >> 3) * K_DIM + kf * 4;  // token = l/TOPK
    const float* Bp   = B + ((size_t)e * N_DIM + n0 + srow) * K_DIM + kf * 4;

    float acc[2][4];
#pragma unroll
    for (int i = 0; i < 2; i++)
#pragma unroll
        for (int k = 0; k < 4; k++) acc[i][k] = 0.f;

    // --- prologue: fill STAGES-1 pipeline stages ---
#pragma unroll
    for (int s = 0; s < STAGES - 1; s++) {
        float* As = smem + s * STAGE_WORDS;
        float* Bs = As + AS_WORDS;
        const int k0 = s * BK;
        cp16(As + srow * STRIDE + kf * 4, arow + k0);
#pragma unroll
        for (int j = 0; j < 2; j++)
            cp16(Bs + (srow + j * 32) * STRIDE + kf * 4, Bp + (size_t)j * 32 * K_DIM + k0);
        cp_commit();
    }

    // fragment-load lane mapping (k-relabel: thread q=lane&3 owns global k q*8..q*8+7)
    const int q  = lane & 3;
    const int r0 = lane >> 2;
    const int fragoff = q * 8;

    // --- main loop: one sync per tile, loads always 2 tiles ahead ---
    for (int kt = 0; kt < NTILES; kt++) {
        cp_wait<STAGES - 2>();   // tile kt's group complete
        __syncthreads();

        const int ktn = kt + STAGES - 1;
        if (ktn < NTILES) {
            const int stage = ktn % STAGES;
            float* As = smem + stage * STAGE_WORDS;
            float* Bs = As + AS_WORDS;
            const int k0 = ktn * BK;
            cp16(As + srow * STRIDE + kf * 4, arow + k0);
#pragma unroll
            for (int j = 0; j < 2; j++)
                cp16(Bs + (srow + j * 32) * STRIDE + kf * 4, Bp + (size_t)j * 32 * K_DIM + k0);
        }
        cp_commit();

        // compute current stage; warp tile = rows 0..31, cols warp*8..warp*8+7
        const uint32_t* As = (const uint32_t*)(smem + (kt % STAGES) * STAGE_WORDS);
        const uint32_t* Bs = As + AS_WORDS;
        const uint32_t* Ar = As + r0 * STRIDE + fragoff;
        const uint32_t* Bq = Bs + (warp * 8 + r0) * STRIDE + fragoff;

#pragma unroll
        for (int p = 0; p < 2; p++) {   // each p covers mma steps kk=2p, 2p+1
            uint4 a0 = *(const uint4*)(Ar +  0 * STRIDE + p * 4);
            uint4 a1 = *(const uint4*)(Ar +  8 * STRIDE + p * 4);
            uint4 a2 = *(const uint4*)(Ar + 16 * STRIDE + p * 4);
            uint4 a3 = *(const uint4*)(Ar + 24 * STRIDE + p * 4);
            uint4 b0 = *(const uint4*)(Bq + p * 4);
            // kk = 2p: x = (j=q), y = (j=q+4)
            mma_tf32(acc[0], a0.x, a1.x, a0.y, a1.y, b0.x, b0.y);
            mma_tf32(acc[1], a2.x, a3.x, a2.y, a3.y, b0.x, b0.y);
            // kk = 2p+1: z = (j=q), w = (j=q+4)
            mma_tf32(acc[0], a0.z, a1.z, a0.w, a1.w, b0.z, b0.w);
            mma_tf32(acc[1], a2.z, a3.z, a2.w, a3.w, b0.z, b0.w);
        }
    }

    // --- epilogue: (acc + bias[e][n]) * w[l], scattered to out[l] ---
#pragma unroll
    for (int mf = 0; mf < 2; mf++) {
        int r   = mf * 16 + (lane >> 2);
        int col = n0 + warp * 8 + (lane & 3) * 2;
        float2 bv = *(const float2*)(bias + (size_t)e * N_DIM + col);
        {
            int l = sSlot[r]; float wv = sW[r];
            float2 o = { (acc[mf][0] + bv.x) * wv,
                         (acc[mf][1] + bv.y) * wv };
            *(float2*)(out + (size_t)l * N_DIM + col) = o;
        }
        {
            int l = sSlot[r + 8]; float wv = sW[r + 8];
            float2 o = { (acc[mf][2] + bv.x) * wv,
                         (acc[mf][3] + bv.y) * wv };
            *(float2*)(out + (size_t)l * N_DIM + col) = o;
        }
    }
}

extern "C" void kernel_launch(void* const* d_in, const int* in_sizes, int n_in,
                              void* d_out, int out_size) {
    (void)in_sizes; (void)n_in; (void)out_size;
    const float* A    = (const float*)d_in[0];   // [M, K] fp32
    const float* B    = (const float*)d_in[1];   // [E, N, K] fp32
    const float* bias = (const float*)d_in[2];   // [E, N] fp32
    const float* tw   = (const float*)d_in[3];   // [M, TOPK] fp32
    const int*   ids  = (const int*)d_in[4];     // [M, TOPK] int32
    float* out = (float*)d_out;                  // [M, TOPK, N] fp32

    static bool attr_set = false;
    if (!attr_set) {
        cudaFuncSetAttribute(moe_fused_kernel,
                             cudaFuncAttributeMaxDynamicSharedMemorySize, SMEM_BYTES);
        attr_set = true;
    }
    moe_fused_kernel<<<dim3(N_DIM / BN, E_NUM), THREADS, SMEM_BYTES>>>(
        A, B, bias, tw, ids, out);
}

// round 14
// speedup vs baseline: 1.1207x; 1.1207x over previous
#include <cuda_runtime.h>
#include <cuda.h>
#include <cstdint>

// Problem constants (fixed by the reference)
#define M_TOK 256
#define K_DIM 1024
#define N_DIM 2048
#define E_NUM 64
#define TOPK  8
#define L_ROWS (M_TOK * TOPK)     // 2048 routed rows
#define CAP    32                 // rows per expert (balanced routing, exact)

// GEMM tiling
#define BM 32
#define BN 128
#define BK 32
#define THREADS 256               // 8 warps; each warp owns 32m x 16n
#define STAGES 5
#define NTILES (K_DIM / BK)       // 32

#define B_STAGE_WORDS (BN * BK)   // 4096 words = 16 KB (TMA box, dense SW128)
#define A_STAGE_WORDS (BM * BK)   // 1024 words = 4 KB (cp.async, manual SW128)
#define B_STAGE_BYTES (B_STAGE_WORDS * 4)
#define SMEM_BYTES (STAGES * (B_STAGE_WORDS + A_STAGE_WORDS) * 4)  // 102400 -> 2 blocks/SM

// TMA + SW128 requires the SMEM destination aligned to the 1024B swizzle span.
extern __shared__ __align__(1024) float smem[];   // [B stages (16KB each)][A stages]

__device__ __forceinline__ uint32_t s2u(const void* p) {
    return (uint32_t)__cvta_generic_to_shared(p);
}

__device__ __forceinline__ void cp16(float* dst_smem, const float* src) {
    uint32_t d = s2u(dst_smem);
    asm volatile("cp.async.cg.shared.global [%0], [%1], 16;" :: "r"(d), "l"(src));
}
__device__ __forceinline__ void cp_commit() {
    asm volatile("cp.async.commit_group;");
}
template <int N>
__device__ __forceinline__ void cp_wait() {
    asm volatile("cp.async.wait_group %0;" :: "n"(N));
}

__device__ __forceinline__ void mbar_init(uint32_t addr, uint32_t count) {
    asm volatile("mbarrier.init.shared.b64 [%0], %1;" :: "r"(addr), "r"(count) : "memory");
}
__device__ __forceinline__ void mbar_expect_tx(uint32_t addr, uint32_t bytes) {
    asm volatile("mbarrier.arrive.expect_tx.shared.b64 _, [%0], %1;"
                 :: "r"(addr), "r"(bytes) : "memory");
}
__device__ __forceinline__ void mbar_wait(uint32_t addr, uint32_t parity) {
    asm volatile(
        "{\n\t.reg .pred P;\n\t"
        "W%=:\n\t"
        "mbarrier.try_wait.parity.shared.b64 P, [%0], %1;\n\t"
        "@P bra D%=;\n\t"
        "bra W%=;\n\t"
        "D%=:\n\t}"
        :: "r"(addr), "r"(parity) : "memory");
}
__device__ __forceinline__ void tma_load_2d(uint32_t dst, const CUtensorMap* map,
                                            int cx, int cy, uint32_t mbar) {
    asm volatile(
        "cp.async.bulk.tensor.2d.shared::cta.global.tile.mbarrier::complete_tx::bytes "
        "[%0], [%1, {%2, %3}], [%4];"
        :: "r"(dst), "l"(map), "r"(cx), "r"(cy), "r"(mbar) : "memory");
}

__device__ __forceinline__ void mma_tf32(float c[4],
                                         uint32_t a0, uint32_t a1, uint32_t a2, uint32_t a3,
                                         uint32_t b0, uint32_t b1) {
    asm volatile(
        "mma.sync.aligned.m16n8k8.row.col.f32.tf32.tf32.f32 "
        "{%0,%1,%2,%3}, {%4,%5,%6,%7}, {%8,%9}, {%0,%1,%2,%3};"
        : "+f"(c[0]), "+f"(c[1]), "+f"(c[2]), "+f"(c[3])
        : "r"(a0), "r"(a1), "r"(a2), "r"(a3), "r"(b0), "r"(b1));
}

// ---------------------------------------------------------------------------
// Fused routing + grouped GEMM. B tiles (16KB) stream via 2D TMA (SW128,
// mbarrier expect_tx), A gathered rows via cp.async with matching manual
// SW128 quad swizzle. 5-stage pipeline, one __syncthreads per tile. Raw
// fp32 bits -> tf32 MMA hardware truncation (rel_err ~4.2e-4 < 1e-3).
// ---------------------------------------------------------------------------
__global__ __launch_bounds__(THREADS, 2) void moe_fused_kernel(
    const __grid_constant__ CUtensorMap tmapB,   // B viewed as [E*N rows, K cols]
    const float* __restrict__ A,      // [M, K]
    const float* __restrict__ bias,   // [E, N]
    const float* __restrict__ tw,     // [M, TOPK] flat
    const int*   __restrict__ ids,    // [M, TOPK] flat
    float* __restrict__ out)          // [L, N]
{
    __shared__ int   sSlot[CAP];
    __shared__ float sW[CAP];
    __shared__ int   sCnt;
    __shared__ alignas(8) uint64_t mbar[STAGES];

    const int e    = blockIdx.y;
    const int n0   = blockIdx.x * BN;
    const int t    = threadIdx.x;
    const int warp = t >> 5;
    const int lane = t & 31;

    float* const Bbase = smem;                               // STAGES * 16KB (1024B-aligned)
    float* const Abase = smem + STAGES * B_STAGE_WORDS;      // STAGES * 4KB

    // --- init barriers + routing ---
    if (t == 0) {
        sCnt = 0;
#pragma unroll
        for (int s = 0; s < STAGES; s++) mbar_init(s2u(&mbar[s]), 1);
        asm volatile("prefetch.tensormap [%0];" :: "l"(&tmapB));
    }
    __syncthreads();
    for (int l = t; l < L_ROWS; l += THREADS) {
        if (ids[l] == e) {
            int p = atomicAdd(&sCnt, 1);
            sSlot[p] = l;
        }
    }
    __syncthreads();
    if (t < CAP) sW[t] = tw[sSlot[t]];
    __syncthreads();

    // --- staging mapping: A via cp.async with SW128 quad swizzle ---
    const int srow = t >> 3;                  // 0..31: A row
    const int kf   = t & 7;                   // 16B quad along k
    const int adst = srow * BK + ((kf ^ (srow & 7)) << 2);   // swizzled word offset
    const float* arow = A + (size_t)(sSlot[srow] >> 3) * K_DIM + kf * 4;  // token = l/TOPK
    const int browbase = e * N_DIM + n0;      // TMA y-coordinate

    float acc[2][2][4];
#pragma unroll
    for (int i = 0; i < 2; i++)
#pragma unroll
        for (int j = 0; j < 2; j++)
#pragma unroll
            for (int k = 0; k < 4; k++) acc[i][j][k] = 0.f;

    // --- prologue: fill STAGES-1 stages ---
#pragma unroll
    for (int s = 0; s < STAGES - 1; s++) {
        cp16(Abase + s * A_STAGE_WORDS + adst, arow + s * BK);
        cp_commit();
        if (t == 0) {
            mbar_expect_tx(s2u(&mbar[s]), B_STAGE_BYTES);
            tma_load_2d(s2u(Bbase + s * B_STAGE_WORDS), &tmapB,
                        s * BK, browbase, s2u(&mbar[s]));
        }
    }

    // fragment-load lane mapping (k-relabel + SW128 quad XOR)
    const int q  = lane & 3;                  // owns global k q*8..q*8+7
    const int r0 = lane >> 2;
    const int qa = ((q << 1) ^ r0) << 2;      // p=0 swizzled quad word offset

    // --- main loop: one sync per tile, TMA/cp.async run STAGES-1 ahead ---
    for (int kt = 0; kt < NTILES; kt++) {
        cp_wait<STAGES - 2>();                        // A tile kt resident
        mbar_wait(s2u(&mbar[kt % STAGES]), (kt / STAGES) & 1);  // B tile kt resident
        __syncthreads();                              // stage (kt-1)%S now reusable

        const int ktn = kt + STAGES - 1;
        if (ktn < NTILES) {
            const int stage = ktn % STAGES;
            cp16(Abase + stage * A_STAGE_WORDS + adst, arow + ktn * BK);
            if (t == 0) {
                mbar_expect_tx(s2u(&mbar[stage]), B_STAGE_BYTES);
                tma_load_2d(s2u(Bbase + stage * B_STAGE_WORDS), &tmapB,
                            ktn * BK, browbase, s2u(&mbar[stage]));
            }
        }
        cp_commit();   // always commit (keeps wait_group arithmetic exact)

        // compute; warp tile = rows 0..31, cols warp*16..+15
        const uint32_t* Au = (const uint32_t*)(Abase + (kt % STAGES) * A_STAGE_WORDS);
        const uint32_t* Bu = (const uint32_t*)(Bbase + (kt % STAGES) * B_STAGE_WORDS);
        const uint32_t* Ar = Au + r0 * BK;
        const uint32_t* Br = Bu + (warp * 16 + r0) * BK;

#pragma unroll
        for (int p = 0; p < 2; p++) {     // p covers mma steps kk=2p, 2p+1
            const int qo = qa ^ (p << 2); // quad' = (2q+p) ^ r0
            uint4 a0 = *(const uint4*)(Ar +  0 * BK + qo);
            uint4 a1 = *(const uint4*)(Ar +  8 * BK + qo);
            uint4 a2 = *(const uint4*)(Ar + 16 * BK + qo);
            uint4 a3 = *(const uint4*)(Ar + 24 * BK + qo);
            uint4 b0 = *(const uint4*)(Br +  0 * BK + qo);
            uint4 b1 = *(const uint4*)(Br +  8 * BK + qo);
            // kk = 2p: x = (j=q), y = (j=q+4)
            mma_tf32(acc[0][0], a0.x, a1.x, a0.y, a1.y, b0.x, b0.y);
            mma_tf32(acc[1][0], a2.x, a3.x, a2.y, a3.y, b0.x, b0.y);
            mma_tf32(acc[0][1], a0.x, a1.x, a0.y, a1.y, b1.x, b1.y);
            mma_tf32(acc[1][1], a2.x, a3.x, a2.y, a3.y, b1.x, b1.y);
            // kk = 2p+1: z = (j=q), w = (j=q+4)
            mma_tf32(acc[0][0], a0.z, a1.z, a0.w, a1.w, b0.z, b0.w);
            mma_tf32(acc[1][0], a2.z, a3.z, a2.w, a3.w, b0.z, b0.w);
            mma_tf32(acc[0][1], a0.z, a1.z, a0.w, a1.w, b1.z, b1.w);
            mma_tf32(acc[1][1], a2.z, a3.z, a2.w, a3.w, b1.z, b1.w);
        }
    }

    // --- epilogue: (acc + bias[e][n]) * w[l], scattered to out[l] ---
#pragma unroll
    for (int mf = 0; mf < 2; mf++) {
#pragma unroll
        for (int nf = 0; nf < 2; nf++) {
            int r   = mf * 16 + (lane >> 2);
            int col = n0 + warp * 16 + nf * 8 + (lane & 3) * 2;
            float2 bv = *(const float2*)(bias + (size_t)e * N_DIM + col);
            {
                int l = sSlot[r]; float wv = sW[r];
                float2 o = { (acc[mf][nf][0] + bv.x) * wv,
                             (acc[mf][nf][1] + bv.y) * wv };
                *(float2*)(out + (size_t)l * N_DIM + col) = o;
            }
            {
                int l = sSlot[r + 8]; float wv = sW[r + 8];
                float2 o = { (acc[mf][nf][2] + bv.x) * wv,
                             (acc[mf][nf][3] + bv.y) * wv };
                *(float2*)(out + (size_t)l * N_DIM + col) = o;
            }
        }
    }
}

// ---------------------------------------------------------------------------
// Host side: build the B tensor map (driver entry point via cudart — no -lcuda)
// ---------------------------------------------------------------------------
typedef CUresult (*encode_fn_t)(CUtensorMap*, CUtensorMapDataType, cuuint32_t, void*,
                                const cuuint64_t*, const cuuint64_t*, const cuuint32_t*,
                                const cuuint32_t*, CUtensorMapInterleave, CUtensorMapSwizzle,
                                CUtensorMapL2promotion, CUtensorMapFloatOOBfill);

extern "C" void kernel_launch(void* const* d_in, const int* in_sizes, int n_in,
                              void* d_out, int out_size) {
    (void)in_sizes; (void)n_in; (void)out_size;
    const float* A    = (const float*)d_in[0];   // [M, K] fp32
    const float* B    = (const float*)d_in[1];   // [E, N, K] fp32
    const float* bias = (const float*)d_in[2];   // [E, N] fp32
    const float* tw   = (const float*)d_in[3];   // [M, TOPK] fp32
    const int*   ids  = (const int*)d_in[4];     // [M, TOPK] int32
    float* out = (float*)d_out;                  // [M, TOPK, N] fp32

    encode_fn_t encode = nullptr;
    cudaDriverEntryPointQueryResult qr;
    cudaGetDriverEntryPoint("cuTensorMapEncodeTiled", (void**)&encode,
                            cudaEnableDefault, &qr);

    CUtensorMap tmapB;
    {
        cuuint64_t dims[2]    = {(cuuint64_t)K_DIM, (cuuint64_t)(E_NUM * N_DIM)};
        cuuint64_t strides[1] = {(cuuint64_t)K_DIM * sizeof(float)};
        cuuint32_t box[2]     = {BK, BN};          // 32 floats (128B) x 128 rows
        cuuint32_t elemstr[2] = {1, 1};
        encode(&tmapB, CU_TENSOR_MAP_DATA_TYPE_FLOAT32, 2, (void*)B,
               dims, strides, box, elemstr,
               CU_TENSOR_MAP_INTERLEAVE_NONE, CU_TENSOR_MAP_SWIZZLE_128B,
               CU_TENSOR_MAP_L2_PROMOTION_L2_128B, CU_TENSOR_MAP_FLOAT_OOB_FILL_NONE);
    }

    static bool attr_set = false;
    if (!attr_set) {
        cudaFuncSetAttribute(moe_fused_kernel,
                             cudaFuncAttributeMaxDynamicSharedMemorySize, SMEM_BYTES);
        attr_set = true;
    }
    moe_fused_kernel<<<dim3(N_DIM / BN, E_NUM), THREADS, SMEM_BYTES>>>(
        tmapB, A, bias, tw, ids, out);
}

// round 15
// speedup vs baseline: 1.1626x; 1.0374x over previous
#include <cuda_runtime.h>
#include <cuda.h>
#include <cstdint>

// Problem constants (fixed by the reference)
#define M_TOK 256
#define K_DIM 1024
#define N_DIM 2048
#define E_NUM 64
#define TOPK  8
#define L_ROWS (M_TOK * TOPK)     // 2048 routed rows
#define CAP    32                 // rows per expert (balanced routing, exact)

// GEMM tiling
#define BM 32
#define BN 128
#define BK 32
#define THREADS 256               // 8 warps; each warp owns 32m x 16n
#define STAGES 4                  // 32 tiles % 4 == 0 -> parity is unit-invariant
#define NTILES (K_DIM / BK)       // 32
#define NX (N_DIM / BN)           // 16 n-tiles per expert
#define TOTAL_UNITS (E_NUM * NX)  // 1024 work units

#define B_STAGE_WORDS (BN * BK)   // 4096 words = 16 KB (TMA box, dense SW128)
#define A_STAGE_WORDS (BM * BK)   // 1024 words = 4 KB (cp.async, manual SW128)
#define B_STAGE_BYTES (B_STAGE_WORDS * 4)
#define SMEM_BYTES (STAGES * (B_STAGE_WORDS + A_STAGE_WORDS) * 4)  // 81920 -> 2 blocks/SM

// persistent work queue
__device__ unsigned int g_next;

// TMA + SW128 requires the SMEM destination aligned to the 1024B swizzle span.
extern __shared__ __align__(1024) float smem[];   // [B stages (16KB each)][A stages]

__device__ __forceinline__ uint32_t s2u(const void* p) {
    return (uint32_t)__cvta_generic_to_shared(p);
}

__device__ __forceinline__ void cp16(float* dst_smem, const float* src) {
    uint32_t d = s2u(dst_smem);
    asm volatile("cp.async.cg.shared.global [%0], [%1], 16;" :: "r"(d), "l"(src));
}
__device__ __forceinline__ void cp_commit() {
    asm volatile("cp.async.commit_group;");
}
template <int N>
__device__ __forceinline__ void cp_wait() {
    asm volatile("cp.async.wait_group %0;" :: "n"(N));
}

__device__ __forceinline__ void mbar_init(uint32_t addr, uint32_t count) {
    asm volatile("mbarrier.init.shared.b64 [%0], %1;" :: "r"(addr), "r"(count) : "memory");
}
__device__ __forceinline__ void mbar_expect_tx(uint32_t addr, uint32_t bytes) {
    asm volatile("mbarrier.arrive.expect_tx.shared.b64 _, [%0], %1;"
                 :: "r"(addr), "r"(bytes) : "memory");
}
__device__ __forceinline__ void mbar_wait(uint32_t addr, uint32_t parity) {
    asm volatile(
        "{\n\t.reg .pred P;\n\t"
        "W%=:\n\t"
        "mbarrier.try_wait.parity.shared.b64 P, [%0], %1;\n\t"
        "@P bra D%=;\n\t"
        "bra W%=;\n\t"
        "D%=:\n\t}"
        :: "r"(addr), "r"(parity) : "memory");
}
__device__ __forceinline__ void tma_load_2d(uint32_t dst, const CUtensorMap* map,
                                            int cx, int cy, uint32_t mbar) {
    asm volatile(
        "cp.async.bulk.tensor.2d.shared::cta.global.tile.mbarrier::complete_tx::bytes "
        "[%0], [%1, {%2, %3}], [%4];"
        :: "r"(dst), "l"(map), "r"(cx), "r"(cy), "r"(mbar) : "memory");
}

__device__ __forceinline__ void mma_tf32(float c[4],
                                         uint32_t a0, uint32_t a1, uint32_t a2, uint32_t a3,
                                         uint32_t b0, uint32_t b1) {
    asm volatile(
        "mma.sync.aligned.m16n8k8.row.col.f32.tf32.tf32.f32 "
        "{%0,%1,%2,%3}, {%4,%5,%6,%7}, {%8,%9}, {%0,%1,%2,%3};"
        : "+f"(c[0]), "+f"(c[1]), "+f"(c[2]), "+f"(c[3])
        : "r"(a0), "r"(a1), "r"(a2), "r"(a3), "r"(b0), "r"(b1));
}

__global__ void reset_next_kernel() { g_next = 0; }

// ---------------------------------------------------------------------------
// Persistent fused MoE grouped GEMM. 2 blocks/SM pop (expert, n-tile) units
// from a global atomic queue until empty — eliminates the 3.46-wave
// quantization tail of the 1024-block launch. Per unit: routing scan, 4-stage
// TMA(B,SW128)/cp.async(A) pipeline over K, fused bias+weight+scatter
// epilogue. 32 tiles % 4 stages == 0 so mbarrier parity depends only on kt
// and units chain without re-init. Raw fp32 -> tf32 MMA truncation
// (rel_err 4.2e-4, verified).
// ---------------------------------------------------------------------------
__global__ __launch_bounds__(THREADS, 2) void moe_fused_kernel(
    const __grid_constant__ CUtensorMap tmapB,   // B viewed as [E*N rows, K cols]
    const float* __restrict__ A,      // [M, K]
    const float* __restrict__ bias,   // [E, N]
    const float* __restrict__ tw,     // [M, TOPK] flat
    const int*   __restrict__ ids,    // [M, TOPK] flat
    float* __restrict__ out)          // [L, N]
{
    __shared__ int   sSlot[CAP];
    __shared__ float sW[CAP];
    __shared__ int   sCnt;
    __shared__ int   sU;
    __shared__ alignas(8) uint64_t mbar[STAGES];

    const int t    = threadIdx.x;
    const int warp = t >> 5;
    const int lane = t & 31;

    float* const Bbase = smem;                               // STAGES * 16KB (1024B-aligned)
    float* const Abase = smem + STAGES * B_STAGE_WORDS;      // STAGES * 4KB

    if (t == 0) {
#pragma unroll
        for (int s = 0; s < STAGES; s++) mbar_init(s2u(&mbar[s]), 1);
        asm volatile("prefetch.tensormap [%0];" :: "l"(&tmapB));
    }
    __syncthreads();

    // staging mapping (fixed per thread)
    const int srow = t >> 3;                  // 0..31: A row
    const int kf   = t & 7;                   // 16B quad along k
    const int adst = srow * BK + ((kf ^ (srow & 7)) << 2);   // SW128 word offset
    // fragment-load lane mapping (k-relabel + SW128 quad XOR)
    const int q  = lane & 3;                  // owns global k q*8..q*8+7
    const int r0 = lane >> 2;
    const int qa = ((q << 1) ^ r0) << 2;      // p=0 swizzled quad word offset

    for (;;) {
        // --- pop a work unit ---
        if (t == 0) { sU = (int)atomicAdd(&g_next, 1u); sCnt = 0; }
        __syncthreads();
        const int u = sU;
        if (u >= TOTAL_UNITS) break;
        const int e  = u >> 4;
        const int n0 = (u & (NX - 1)) * BN;

        // --- routing: bucket this expert's 32 slots (order-invariant) ---
        for (int l = t; l < L_ROWS; l += THREADS) {
            if (ids[l] == e) {
                int p = atomicAdd(&sCnt, 1);
                sSlot[p] = l;
                sW[p]    = tw[l];
            }
        }
        __syncthreads();

        const float* arow = A + (size_t)(sSlot[srow] >> 3) * K_DIM + kf * 4;  // token = l/TOPK
        const int browbase = e * N_DIM + n0;  // TMA y-coordinate

        float acc[2][2][4];
#pragma unroll
        for (int i = 0; i < 2; i++)
#pragma unroll
            for (int j = 0; j < 2; j++)
#pragma unroll
                for (int k = 0; k < 4; k++) acc[i][j][k] = 0.f;

        // --- prologue: fill STAGES-1 stages ---
#pragma unroll
        for (int s = 0; s < STAGES - 1; s++) {
            cp16(Abase + s * A_STAGE_WORDS + adst, arow + s * BK);
            cp_commit();
            if (t == 0) {
                mbar_expect_tx(s2u(&mbar[s]), B_STAGE_BYTES);
                tma_load_2d(s2u(Bbase + s * B_STAGE_WORDS), &tmapB,
                            s * BK, browbase, s2u(&mbar[s]));
            }
        }

        // --- main loop over K tiles ---
        for (int kt = 0; kt < NTILES; kt++) {
            const int stage = kt & (STAGES - 1);
            cp_wait<STAGES - 2>();                       // A tile kt resident
            mbar_wait(s2u(&mbar[stage]), (kt >> 2) & 1); // B tile kt resident
            __syncthreads();                             // prior stage reusable

            const int ktn = kt + STAGES - 1;
            if (ktn < NTILES) {
                const int ns = ktn & (STAGES - 1);
                cp16(Abase + ns * A_STAGE_WORDS + adst, arow + ktn * BK);
                if (t == 0) {
                    mbar_expect_tx(s2u(&mbar[ns]), B_STAGE_BYTES);
                    tma_load_2d(s2u(Bbase + ns * B_STAGE_WORDS), &tmapB,
                                ktn * BK, browbase, s2u(&mbar[ns]));
                }
            }
            cp_commit();   // one commit per tile keeps wait_group arithmetic exact

            // compute; warp tile = rows 0..31, cols warp*16..+15
            const uint32_t* Au = (const uint32_t*)(Abase + stage * A_STAGE_WORDS);
            const uint32_t* Bu = (const uint32_t*)(Bbase + stage * B_STAGE_WORDS);
            const uint32_t* Ar = Au + r0 * BK;
            const uint32_t* Br = Bu + (warp * 16 + r0) * BK;

#pragma unroll
            for (int p = 0; p < 2; p++) {     // p covers mma steps kk=2p, 2p+1
                const int qo = qa ^ (p << 2); // quad' = (2q+p) ^ r0
                uint4 a0 = *(const uint4*)(Ar +  0 * BK + qo);
                uint4 a1 = *(const uint4*)(Ar +  8 * BK + qo);
                uint4 a2 = *(const uint4*)(Ar + 16 * BK + qo);
                uint4 a3 = *(const uint4*)(Ar + 24 * BK + qo);
                uint4 b0 = *(const uint4*)(Br +  0 * BK + qo);
                uint4 b1 = *(const uint4*)(Br +  8 * BK + qo);
                mma_tf32(acc[0][0], a0.x, a1.x, a0.y, a1.y, b0.x, b0.y);
                mma_tf32(acc[1][0], a2.x, a3.x, a2.y, a3.y, b0.x, b0.y);
                mma_tf32(acc[0][1], a0.x, a1.x, a0.y, a1.y, b1.x, b1.y);
                mma_tf32(acc[1][1], a2.x, a3.x, a2.y, a3.y, b1.x, b1.y);
                mma_tf32(acc[0][0], a0.z, a1.z, a0.w, a1.w, b0.z, b0.w);
                mma_tf32(acc[1][0], a2.z, a3.z, a2.w, a3.w, b0.z, b0.w);
                mma_tf32(acc[0][1], a0.z, a1.z, a0.w, a1.w, b1.z, b1.w);
                mma_tf32(acc[1][1], a2.z, a3.z, a2.w, a3.w, b1.z, b1.w);
            }
        }

        // --- epilogue: (acc + bias[e][n]) * w[l], scattered to out[l] ---
#pragma unroll
        for (int mf = 0; mf < 2; mf++) {
#pragma unroll
            for (int nf = 0; nf < 2; nf++) {
                int r   = mf * 16 + (lane >> 2);
                int col = n0 + warp * 16 + nf * 8 + (lane & 3) * 2;
                float2 bv = *(const float2*)(bias + (size_t)e * N_DIM + col);
                {
                    int l = sSlot[r]; float wv = sW[r];
                    float2 o = { (acc[mf][nf][0] + bv.x) * wv,
                                 (acc[mf][nf][1] + bv.y) * wv };
                    *(float2*)(out + (size_t)l * N_DIM + col) = o;
                }
                {
                    int l = sSlot[r + 8]; float wv = sW[r + 8];
                    float2 o = { (acc[mf][nf][2] + bv.x) * wv,
                                 (acc[mf][nf][3] + bv.y) * wv };
                    *(float2*)(out + (size_t)l * N_DIM + col) = o;
                }
            }
        }
        __syncthreads();   // all warps done with sSlot/sW/smem before next unit
    }
}

// ---------------------------------------------------------------------------
// Host side
// ---------------------------------------------------------------------------
typedef CUresult (*encode_fn_t)(CUtensorMap*, CUtensorMapDataType, cuuint32_t, void*,
                                const cuuint64_t*, const cuuint64_t*, const cuuint32_t*,
                                const cuuint32_t*, CUtensorMapInterleave, CUtensorMapSwizzle,
                                CUtensorMapL2promotion, CUtensorMapFloatOOBfill);

extern "C" void kernel_launch(void* const* d_in, const int* in_sizes, int n_in,
                              void* d_out, int out_size) {
    (void)in_sizes; (void)n_in; (void)out_size;
    const float* A    = (const float*)d_in[0];   // [M, K] fp32
    const float* B    = (const float*)d_in[1];   // [E, N, K] fp32
    const float* bias = (const float*)d_in[2];   // [E, N] fp32
    const float* tw   = (const float*)d_in[3];   // [M, TOPK] fp32
    const int*   ids  = (const int*)d_in[4];     // [M, TOPK] int32
    float* out = (float*)d_out;                  // [M, TOPK, N] fp32

    encode_fn_t encode = nullptr;
    cudaDriverEntryPointQueryResult qr;
    cudaGetDriverEntryPoint("cuTensorMapEncodeTiled", (void**)&encode,
                            cudaEnableDefault, &qr);

    CUtensorMap tmapB;
    {
        cuuint64_t dims[2]    = {(cuuint64_t)K_DIM, (cuuint64_t)(E_NUM * N_DIM)};
        cuuint64_t strides[1] = {(cuuint64_t)K_DIM * sizeof(float)};
        cuuint32_t box[2]     = {BK, BN};          // 32 floats (128B) x 128 rows
        cuuint32_t elemstr[2] = {1, 1};
        encode(&tmapB, CU_TENSOR_MAP_DATA_TYPE_FLOAT32, 2, (void*)B,
               dims, strides, box, elemstr,
               CU_TENSOR_MAP_INTERLEAVE_NONE, CU_TENSOR_MAP_SWIZZLE_128B,
               CU_TENSOR_MAP_L2_PROMOTION_L2_128B, CU_TENSOR_MAP_FLOAT_OOB_FILL_NONE);
    }

    static int nblocks = 0;
    if (nblocks == 0) {
        int smc = 0;
        cudaDeviceGetAttribute(&smc, cudaDevAttrMultiProcessorCount, 0);
        nblocks = 2 * smc;
        cudaFuncSetAttribute(moe_fused_kernel,
                             cudaFuncAttributeMaxDynamicSharedMemorySize, SMEM_BYTES);
    }

    reset_next_kernel<<<1, 1>>>();
    moe_fused_kernel<<<nblocks, THREADS, SMEM_BYTES>>>(
        tmapB, A, bias, tw, ids, out);
}